// round 13
// baseline (speedup 1.0000x reference)
#include <cuda_runtime.h>
#include <cuda_bf16.h>
#include <math.h>

// ---------------- problem constants ----------------
#define TT 512
#define BB 64
#define II 256
#define HH 1024
#define AA 128
#define OO 1024
#define PSZ0 13568            // I + 13H
#define PSZ1 14336            // H + 13O
#define NB 256                // persistent CTAs (2/SM on 128 SMs; safe residency)
#define BIGB (1 << 30)

// ---------------- bf16 weight buffer offsets (elements) ----------------
#define OFF_AW0 0             // 512 x 1408
#define OFF_AH0 720896        // 512 x 128
#define OFF_PW0 786432        // 13568 x 128
#define OFF_FW0 2523136       // 4096 x 256
#define OFF_FH0 3571712       // 4096 x 1024
#define OFF_AW1 7766016       // 512 x 2176
#define OFF_AH1 8880128       // 512 x 128
#define OFF_PW1 8945664       // 14336 x 128
#define OFF_FW1 10780672      // 4096 x 1024
#define OFF_FH1 14974976      // 4096 x 1024
#define TOTW    19169280

// ---------------- device scratch (static, no runtime alloc) ----------------
__device__ __nv_bfloat16 g_whi[TOTW];
__device__ __nv_bfloat16 g_wlo[TOTW];
__device__ float g_partF[10 * 64 * 4096];   // fcell split-K partials (S3:10, S6:4)
__device__ float g_partA[36 * 64 * 512];    // adapt split-K partials (S1:24, S4:36)
__device__ float g_ahe [64 * PSZ1];         // policy output (single buffer)
__device__ float g_a0x[BB * AA];
__device__ float g_a0c[BB * AA];
__device__ float g_a1x[BB * AA];
__device__ float g_a1c[BB * AA];
__device__ float g_f0x[BB * HH];
__device__ float g_f0c[BB * HH];
__device__ float g_f1x[BB * OO];
__device__ float g_f1c[BB * OO];
__device__ unsigned g_cnt = 0;
__device__ unsigned g_gen = 0;

__device__ __forceinline__ float sigf(float x) { return 1.0f / (1.0f + __expf(-x)); }

// ---------------- helpers ----------------
__device__ __forceinline__ unsigned pkb(__nv_bfloat16 a, __nv_bfloat16 b) {
    return (unsigned)__bfloat16_as_ushort(a) | ((unsigned)__bfloat16_as_ushort(b) << 16);
}
// split two fp32 -> packed hi pair + lo pair
__device__ __forceinline__ void split2(float x, float y, unsigned& h, unsigned& l) {
    __nv_bfloat16 hx = __float2bfloat16(x), hy = __float2bfloat16(y);
    __nv_bfloat16 lx = __float2bfloat16(x - __bfloat162float(hx));
    __nv_bfloat16 ly = __float2bfloat16(y - __bfloat162float(hy));
    h = pkb(hx, hy); l = pkb(lx, ly);
}
__device__ __forceinline__ void mma_bf16(float* c, const unsigned* a, const unsigned* b) {
    asm volatile(
        "mma.sync.aligned.m16n8k16.row.col.f32.bf16.bf16.f32 "
        "{%0,%1,%2,%3}, {%4,%5,%6,%7}, {%8,%9}, {%0,%1,%2,%3};\n"
        : "+f"(c[0]), "+f"(c[1]), "+f"(c[2]), "+f"(c[3])
        : "r"(a[0]), "r"(a[1]), "r"(a[2]), "r"(a[3]), "r"(b[0]), "r"(b[1]));
}

// ---------------- grid-wide barrier ----------------
__device__ __forceinline__ void gsync() {
    __syncthreads();
    if (threadIdx.x == 0) {
        unsigned gen = *(volatile unsigned*)&g_gen;
        __threadfence();                       // release
        if (atomicInc(&g_cnt, NB - 1) == NB - 1) {
            atomicAdd(&g_gen, 1);
        } else {
            while (*(volatile unsigned*)&g_gen == gen) { __nanosleep(32); }
        }
        __threadfence();                       // acquire (L1 invalidate)
    }
    __syncthreads();
}

// ---------------- prefetch one 32-k sub-block into registers ----------------
struct Pf { float4 pa[2]; uint2 wh[2]; uint2 wl[2]; };

__device__ __forceinline__ void prefetch_sub(
    int kk, int tid, int tile,
    const float* __restrict__ A0, const float* __restrict__ A1,
    const float* __restrict__ A2, const float* __restrict__ A3,
    int s0, int s1, int s2, int s3, int b0, int b1, int b2,
    const float* __restrict__ scP, int sstr,
    const __nv_bfloat16* __restrict__ Wh0, const __nv_bfloat16* __restrict__ Wl0, int w0s,
    const __nv_bfloat16* __restrict__ Wh1, const __nv_bfloat16* __restrict__ Wl1, int w1s,
    int wsplit, Pf& p)
{
    const float* Asrc; int Astr, aloc;
    if      (kk < b0) { Asrc = A0; Astr = s0; aloc = kk;      }
    else if (kk < b1) { Asrc = A1; Astr = s1; aloc = kk - b0; }
    else if (kk < b2) { Asrc = A2; Astr = s2; aloc = kk - b1; }
    else              { Asrc = A3; Astr = s3; aloc = kk - b2; }
#pragma unroll
    for (int it = 0; it < 2; it++) {
        int f = it * 256 + tid, b = f & 63, k4 = (f >> 6) << 2;
        float4 v = *(const float4*)(Asrc + b * Astr + aloc + k4);
        if (scP) {
            float4 s = *(const float4*)(scP + b * sstr + kk + k4);
            v.x *= s.x; v.y *= s.y; v.z *= s.z; v.w *= s.w;
        }
        p.pa[it] = v;
    }
    const __nv_bfloat16 *Whs, *Wls; int Wstr, wloc;
    if (kk < wsplit) { Whs = Wh0; Wls = Wl0; Wstr = w0s; wloc = kk; }
    else             { Whs = Wh1; Wls = Wl1; Wstr = w1s; wloc = kk - wsplit; }
#pragma unroll
    for (int it = 0; it < 2; it++) {
        int f = it * 256 + tid, n = f & 63, k4 = (f >> 6) << 2;
        size_t off = (size_t)(tile * 64 + n) * Wstr + wloc + k4;
        p.wh[it] = *(const uint2*)(Whs + off);
        p.wl[it] = *(const uint2*)(Wls + off);
    }
}

// ---------------- GEMM stage: bf16x3 tensor-core engine ----------------
// C[64 x N] = A[64 x K] @ W[N x K]^T, tile 64 x 64, K chunk KCH (mult of 32).
// 8 warps = 4(m) x 2(n); warp computes 16 x 32 via 4 m16n8k16 column tiles.
// 3-term bf16 split: hi*hi + hi*lo + lo*hi, fp32 accumulate.
__device__ void gemm_mma(
    __nv_bfloat16* sAh, __nv_bfloat16* sAl, __nv_bfloat16* sWh, __nv_bfloat16* sWl,
    int cta0, int nctas, int nunits, int ntiles, int KCH,
    const float* __restrict__ A0, const float* __restrict__ A1,
    const float* __restrict__ A2, const float* __restrict__ A3,
    int s0, int s1, int s2, int s3, int b0, int b1, int b2,
    const float* __restrict__ scP, int sstr,
    const __nv_bfloat16* __restrict__ Wh0, const __nv_bfloat16* __restrict__ Wl0, int w0s,
    const __nv_bfloat16* __restrict__ Wh1, const __nv_bfloat16* __restrict__ Wl1, int w1s,
    int wsplit,
    const float* __restrict__ biasP,
    float* __restrict__ outP, int strideP, int N)
{
    const int tid = threadIdx.x, lane = tid & 31, wid = tid >> 5;
    const int wm = wid & 3, wn = wid >> 2;
    const int r0 = lane >> 2, c0 = (lane & 3) * 2;
    const int bid = (int)blockIdx.x - cta0;
    if (bid < 0 || bid >= nctas) return;

    for (int u = bid; u < nunits; u += nctas) {
        const int tile = u % ntiles, kc = u / ntiles;
        const int kbase = kc * KCH;

        float acc[4][4];
#pragma unroll
        for (int j = 0; j < 4; j++)
#pragma unroll
            for (int i = 0; i < 4; i++) acc[j][i] = 0.0f;

        Pf p;
        prefetch_sub(kbase, tid, tile, A0, A1, A2, A3, s0, s1, s2, s3, b0, b1, b2,
                     scP, sstr, Wh0, Wl0, w0s, Wh1, Wl1, w1s, wsplit, p);

        for (int k0 = 0; k0 < KCH; k0 += 32) {
            __syncthreads();
            // STS A: split fp32 -> hi/lo bf16 (stride 40 elems, conflict-free)
#pragma unroll
            for (int it = 0; it < 2; it++) {
                int f = it * 256 + tid, b = f & 63, k4 = (f >> 6) << 2;
                uint2 h, l;
                split2(p.pa[it].x, p.pa[it].y, h.x, l.x);
                split2(p.pa[it].z, p.pa[it].w, h.y, l.y);
                *(uint2*)(sAh + b * 40 + k4) = h;
                *(uint2*)(sAl + b * 40 + k4) = l;
            }
            // STS W hi/lo (already bf16)
#pragma unroll
            for (int it = 0; it < 2; it++) {
                int f = it * 256 + tid, n = f & 63, k4 = (f >> 6) << 2;
                *(uint2*)(sWh + n * 40 + k4) = p.wh[it];
                *(uint2*)(sWl + n * 40 + k4) = p.wl[it];
            }
            if (k0 + 32 < KCH)
                prefetch_sub(kbase + k0 + 32, tid, tile, A0, A1, A2, A3,
                             s0, s1, s2, s3, b0, b1, b2, scP, sstr,
                             Wh0, Wl0, w0s, Wh1, Wl1, w1s, wsplit, p);
            __syncthreads();
            // compute: 2 slabs of 16 k
#pragma unroll
            for (int s = 0; s < 2; s++) {
                const int kof = s * 16;
                unsigned ahi[4], alo[4];
                const int ar = wm * 16 + r0;
                ahi[0] = *(const unsigned*)(sAh + (ar    ) * 40 + kof + c0);
                ahi[1] = *(const unsigned*)(sAh + (ar + 8) * 40 + kof + c0);
                ahi[2] = *(const unsigned*)(sAh + (ar    ) * 40 + kof + c0 + 8);
                ahi[3] = *(const unsigned*)(sAh + (ar + 8) * 40 + kof + c0 + 8);
                alo[0] = *(const unsigned*)(sAl + (ar    ) * 40 + kof + c0);
                alo[1] = *(const unsigned*)(sAl + (ar + 8) * 40 + kof + c0);
                alo[2] = *(const unsigned*)(sAl + (ar    ) * 40 + kof + c0 + 8);
                alo[3] = *(const unsigned*)(sAl + (ar + 8) * 40 + kof + c0 + 8);
#pragma unroll
                for (int j = 0; j < 4; j++) {
                    const int nb = wn * 32 + j * 8 + r0;
                    unsigned bhi[2], blo[2];
                    bhi[0] = *(const unsigned*)(sWh + nb * 40 + kof + c0);
                    bhi[1] = *(const unsigned*)(sWh + nb * 40 + kof + c0 + 8);
                    blo[0] = *(const unsigned*)(sWl + nb * 40 + kof + c0);
                    blo[1] = *(const unsigned*)(sWl + nb * 40 + kof + c0 + 8);
                    mma_bf16(acc[j], ahi, bhi);
                    mma_bf16(acc[j], ahi, blo);
                    mma_bf16(acc[j], alo, bhi);
                }
            }
        }

        // epilogue
        float* dst = outP + (size_t)kc * strideP;
        const int rr = wm * 16 + r0;
#pragma unroll
        for (int j = 0; j < 4; j++) {
            const int col = tile * 64 + wn * 32 + j * 8 + c0;
            float bx = 0.0f, by = 0.0f;
            if (biasP && kc == 0) { bx = biasP[col]; by = biasP[col + 1]; }
            *(float2*)(dst + (size_t)rr * N + col) =
                make_float2(acc[j][0] + bx, acc[j][1] + by);
            *(float2*)(dst + (size_t)(rr + 8) * N + col) =
                make_float2(acc[j][2] + bx, acc[j][3] + by);
        }
    }
}

// ---------------- adapt (plain LSTM) cell: 32 CTAs starting at cta0 -------
__device__ void adapt_cell(int cta0,
                           const float* __restrict__ part, int nch,
                           const float* __restrict__ bih, const float* __restrict__ bhh,
                           float* __restrict__ xs, float* __restrict__ cs)
{
    int bid = (int)blockIdx.x - cta0;
    if (bid < 0 || bid >= 32) return;
    int idx = bid * 256 + threadIdx.x;          // 8192 = 64*128
    int b = idx >> 7, a = idx & 127;
    const float* p = part + b * 512 + a;
    float g0 = bih[a]       + bhh[a];
    float g1 = bih[128 + a] + bhh[128 + a];
    float g2 = bih[256 + a] + bhh[256 + a];
    float g3 = bih[384 + a] + bhh[384 + a];
    for (int kc = 0; kc < nch; kc++, p += 64 * 512) {
        g0 += p[0]; g1 += p[128]; g2 += p[256]; g3 += p[384];
    }
    float i = sigf(g0), f = sigf(g1), gg = tanhf(g2), o = sigf(g3);
    float c2 = f * cs[idx] + i * gg;
    cs[idx] = c2;
    xs[idx] = o * tanhf(c2);
}

// ---------------- adaptive (f) cell ----------------
__device__ void fcell_cell(int idx0, int stride,
                           const float* __restrict__ part, int nx, int ntot,
                           const float* __restrict__ fb, const float* __restrict__ ahe,
                           int psz, int ninp,
                           float* __restrict__ xs, float* __restrict__ cs,
                           float* __restrict__ out)
{
    for (int idx = idx0; idx < BB * 1024; idx += stride) {
        int b = idx >> 10, h = idx & 1023;
        const float* ab = ahe + (size_t)b * psz;
        float g[4];
#pragma unroll
        for (int q = 0; q < 4; q++) {
            int n = (q << 10) + h;
            const float* p = part + b * 4096 + n;
            float px = 0.0f, ph = 0.0f;
            int kc = 0;
            for (; kc < nx; kc++)   px += p[kc * (64 * 4096)];
            for (; kc < ntot; kc++) ph += p[kc * (64 * 4096)];
            g[q] = px * ab[ninp + 1024 + n] + ph * ab[ninp + 5120 + n]
                 + fb[n] * ab[ninp + 9216 + n];
        }
        float i = sigf(g[0]), f = sigf(g[1]), gg = tanhf(g[2]), o = sigf(g[3]);
        float c2 = f * cs[idx] + i * gg;
        float hx = o * tanhf(c2);
        cs[idx] = c2;
        xs[idx] = hx;
        if (out) out[idx] = hx;
    }
}

// ---------------- weight split kernel (fp32 -> bf16 hi/lo) ----------------
__global__ void conv_w(const float* __restrict__ src,
                       __nv_bfloat16* __restrict__ hi,
                       __nv_bfloat16* __restrict__ lo, int n)
{
    for (int i = blockIdx.x * 256 + threadIdx.x; i < n; i += gridDim.x * 256) {
        float v = src[i];
        __nv_bfloat16 h = __float2bfloat16(v);
        hi[i] = h;
        lo[i] = __float2bfloat16(v - __bfloat162float(h));
    }
}

// ---------------- persistent kernel ----------------
__global__ void __launch_bounds__(256, 2) alstm_persist(
    const float* __restrict__ x,
    const float* __restrict__ a_bih0, const float* __restrict__ a_bhh0,
    const float* __restrict__ p_b0,   const float* __restrict__ f_b0,
    const float* __restrict__ a_bih1, const float* __restrict__ a_bhh1,
    const float* __restrict__ p_b1,   const float* __restrict__ f_b1,
    float* __restrict__ out)
{
    __shared__ __align__(16) __nv_bfloat16 sAh[64 * 40];
    __shared__ __align__(16) __nv_bfloat16 sAl[64 * 40];
    __shared__ __align__(16) __nv_bfloat16 sWh[64 * 40];
    __shared__ __align__(16) __nv_bfloat16 sWl[64 * 40];

    const int gtid = blockIdx.x * 256 + threadIdx.x;

    for (int i = gtid; i < BB * AA; i += NB * 256) {
        g_a0x[i] = 0.0f; g_a0c[i] = 0.0f; g_a1x[i] = 0.0f; g_a1c[i] = 0.0f;
    }
    for (int i = gtid; i < BB * HH; i += NB * 256) {
        g_f0x[i] = 0.0f; g_f0c[i] = 0.0f; g_f1x[i] = 0.0f; g_f1c[i] = 0.0f;
    }
    gsync();

    // S1(0): A=[x0|f0x|a1x|a0x], K=1536, KCH=64 -> 24 chunks x 8 tiles = 192 units
    gemm_mma(sAh, sAl, sWh, sWl, 0, NB, 192, 8, 64,
        x, g_f0x, g_a1x, g_a0x, II, HH, AA, AA, 256, 1280, 1408,
        nullptr, 0,
        g_whi + OFF_AW0, g_wlo + OFF_AW0, 1408,
        g_whi + OFF_AH0, g_wlo + OFF_AH0, 128, 1408,
        nullptr, g_partA, 64 * 512, 512);
    gsync();
    adapt_cell(0, g_partA, 24, a_bih0, a_bhh0, g_a0x, g_a0c);
    gsync();

    for (int t = 0; t < TT; t++) {
        const float* xt = x + (size_t)t * BB * II;

        // A: S2 ahe0 = a0x @ p_w0^T + p_b0, K=128 full -> 212 units
        gemm_mma(sAh, sAl, sWh, sWl, 0, NB, 212, 212, 128,
            g_a0x, g_a0x, g_a0x, g_a0x, AA, AA, AA, AA, BIGB, BIGB, BIGB,
            nullptr, 0,
            g_whi + OFF_PW0, g_wlo + OFF_PW0, 128,
            g_whi + OFF_PW0, g_wlo + OFF_PW0, 128, BIGB,
            p_b0, g_ahe, 0, PSZ0);
        gsync();

        // B: S3 fcell0 GEMM. A=[xt*a_x|f0x*a_h], K=1280, KCH=128 -> 64x10 = 640 units
        gemm_mma(sAh, sAl, sWh, sWl, 0, NB, 640, 64, 128,
            xt, g_f0x, g_f0x, g_f0x, II, HH, HH, HH, 256, BIGB, BIGB,
            g_ahe, PSZ0,
            g_whi + OFF_FW0, g_wlo + OFF_FW0, 256,
            g_whi + OFF_FH0, g_wlo + OFF_FH0, 1024, 256,
            nullptr, g_partF, 64 * 4096, 4096);
        gsync();

        // C: fcell0 (full grid). chunks 0-1 = x, 2-9 = h
        fcell_cell(gtid, NB * 256, g_partF, 2, 10, f_b0, g_ahe, PSZ0, II,
                   g_f0x, g_f0c, nullptr);
        gsync();

        // D: S4 adapt1 GEMM. A=[f0x|f1x|a0x|a1x], K=2304, KCH=64 -> 36x8 = 288 units
        gemm_mma(sAh, sAl, sWh, sWl, 0, NB, 288, 8, 64,
            g_f0x, g_f1x, g_a0x, g_a1x, HH, OO, AA, AA, 1024, 2048, 2176,
            nullptr, 0,
            g_whi + OFF_AW1, g_wlo + OFF_AW1, 2176,
            g_whi + OFF_AH1, g_wlo + OFF_AH1, 128, 2176,
            nullptr, g_partA, 64 * 512, 512);
        gsync();

        // E: adapt1
        adapt_cell(0, g_partA, 36, a_bih1, a_bhh1, g_a1x, g_a1c);
        gsync();

        // F: S5 (CTAs 0-111) || S1(t+1) (CTAs 112-207)
        gemm_mma(sAh, sAl, sWh, sWl, 0, 112, 224, 224, 128,
            g_a1x, g_a1x, g_a1x, g_a1x, AA, AA, AA, AA, BIGB, BIGB, BIGB,
            nullptr, 0,
            g_whi + OFF_PW1, g_wlo + OFF_PW1, 128,
            g_whi + OFF_PW1, g_wlo + OFF_PW1, 128, BIGB,
            p_b1, g_ahe, 0, PSZ1);
        if (t + 1 < TT)
            gemm_mma(sAh, sAl, sWh, sWl, 112, 96, 192, 8, 64,
                x + (size_t)(t + 1) * BB * II, g_f0x, g_a1x, g_a0x,
                II, HH, AA, AA, 256, 1280, 1408,
                nullptr, 0,
                g_whi + OFF_AW0, g_wlo + OFF_AW0, 1408,
                g_whi + OFF_AH0, g_wlo + OFF_AH0, 128, 1408,
                nullptr, g_partA, 64 * 512, 512);
        gsync();

        // G: S6 fcell1 GEMM. A=[f0x*a_x|f1x*a_h], K=2048, KCH=512 -> 64x4 = 256 units
        gemm_mma(sAh, sAl, sWh, sWl, 0, NB, 256, 64, 512,
            g_f0x, g_f1x, g_f1x, g_f1x, HH, OO, OO, OO, 1024, BIGB, BIGB,
            g_ahe, PSZ1,
            g_whi + OFF_FW1, g_wlo + OFF_FW1, 1024,
            g_whi + OFF_FH1, g_wlo + OFF_FH1, 1024, 1024,
            nullptr, g_partF, 64 * 4096, 4096);
        gsync();

        // H: fcell1 (CTAs 0-223) || adapt0(t+1) (CTAs 224-255)
        if (blockIdx.x < 224) {
            fcell_cell(blockIdx.x * 256 + threadIdx.x, 224 * 256,
                       g_partF, 2, 4, f_b1, g_ahe, PSZ1, HH,
                       g_f1x, g_f1c, out + (size_t)t * BB * OO);
        } else if (t + 1 < TT) {
            adapt_cell(224, g_partA, 24, a_bih0, a_bhh0, g_a0x, g_a0c);
        }
        gsync();
    }
}

// ---------------- launcher ----------------
extern "C" void kernel_launch(void* const* d_in, const int* in_sizes, int n_in,
                              void* d_out, int out_size)
{
    __nv_bfloat16 *whi, *wlo;
    cudaGetSymbolAddress((void**)&whi, g_whi);
    cudaGetSymbolAddress((void**)&wlo, g_wlo);

    // split weights into bf16 hi/lo (10 small launches, then 1 persistent)
    conv_w<<<512, 256>>>((const float*)d_in[1],  whi + OFF_AW0, wlo + OFF_AW0, 512 * 1408);
    conv_w<<<512, 256>>>((const float*)d_in[2],  whi + OFF_AH0, wlo + OFF_AH0, 512 * 128);
    conv_w<<<512, 256>>>((const float*)d_in[5],  whi + OFF_PW0, wlo + OFF_PW0, PSZ0 * 128);
    conv_w<<<512, 256>>>((const float*)d_in[7],  whi + OFF_FW0, wlo + OFF_FW0, 4096 * 256);
    conv_w<<<512, 256>>>((const float*)d_in[8],  whi + OFF_FH0, wlo + OFF_FH0, 4096 * 1024);
    conv_w<<<512, 256>>>((const float*)d_in[10], whi + OFF_AW1, wlo + OFF_AW1, 512 * 2176);
    conv_w<<<512, 256>>>((const float*)d_in[11], whi + OFF_AH1, wlo + OFF_AH1, 512 * 128);
    conv_w<<<512, 256>>>((const float*)d_in[14], whi + OFF_PW1, wlo + OFF_PW1, PSZ1 * 128);
    conv_w<<<512, 256>>>((const float*)d_in[16], whi + OFF_FW1, wlo + OFF_FW1, 4096 * 1024);
    conv_w<<<512, 256>>>((const float*)d_in[17], whi + OFF_FH1, wlo + OFF_FH1, 4096 * 1024);

    alstm_persist<<<NB, 256>>>(
        (const float*)d_in[0],
        (const float*)d_in[3],  (const float*)d_in[4],
        (const float*)d_in[6],  (const float*)d_in[9],
        (const float*)d_in[12], (const float*)d_in[13],
        (const float*)d_in[15], (const float*)d_in[18],
        (float*)d_out);
}